// round 5
// baseline (speedup 1.0000x reference)
#include <cuda_runtime.h>
#include <math_constants.h>

// Problem shape (fixed by the dataset): B=64, N=4096, D2=128, S=512
#define D2 128
#define MAXB 64
#define MAXN 4096
#define ECH 8          // e-chunks for qproj

// Scratch (no cudaMalloc allowed)
__device__ float g_qpart[ECH][MAXB * D2];   // 8 partial q arrays (256 KB)
__device__ float g_logits[MAXB * MAXN];     // 1 MB

// ---------------------------------------------------------------------------
// K1: partial q: g_qpart[c][b,d] = sum_{e in chunk c} yq[b,e] * w[e,d]
// grid = (B, ECH), block = 128. Final 8-way reduce folded into K2's q load.
// ---------------------------------------------------------------------------
__global__ __launch_bounds__(128) void qproj_kernel(const float* __restrict__ yq,
                                                    const float* __restrict__ w) {
    const int b = blockIdx.x;
    const int c = blockIdx.y;
    const int d = threadIdx.x;     // 0..127
    __shared__ float syq[D2 / ECH];    // 16
    if (d < D2 / ECH) syq[d] = yq[b * D2 + c * (D2 / ECH) + d];
    __syncthreads();

    const int e0 = c * (D2 / ECH);
    float acc = 0.f;
#pragma unroll
    for (int j = 0; j < D2 / ECH; j++) {
        acc = fmaf(syq[j], w[(e0 + j) * D2 + d], acc);
    }
    g_qpart[c][b * D2 + d] = acc;
}

// ---------------------------------------------------------------------------
// K2: logits[b,n] = q[b] . y_past[b,n]
// 8-lane row-groups: lane (g = lane/8, c = lane%8) owns rows
// row0+g*4..+3, float4 chunks c, c+8, c+16, c+24 of each row.
// 16 front-batched streaming LDG.128 per thread (MLP 16), 3-level
// sub-group shuffle reduce (12 SHFL per 16 rows), one STG.128 per 4 rows.
// Block = 256 threads = 8 warps = 128 rows. grid = (N/128, B).
// ---------------------------------------------------------------------------
__global__ __launch_bounds__(256) void logits_kernel(const float* __restrict__ y_past, int N) {
    const int b = blockIdx.y;
    __shared__ float sq[D2];
    if (threadIdx.x < D2) {
        float s = 0.f;
#pragma unroll
        for (int p = 0; p < ECH; p++) s += g_qpart[p][b * D2 + threadIdx.x];
        sq[threadIdx.x] = s;
    }
    __syncthreads();

    const int warp = threadIdx.x >> 5;     // 0..7
    const int lane = threadIdx.x & 31;
    const int g = lane >> 3;               // 0..3  (row sub-group)
    const int c = lane & 7;                // 0..7  (chunk within row)
    const int row0 = blockIdx.x * 128 + warp * 16 + g * 4;

    const float4* __restrict__ base =
        reinterpret_cast<const float4*>(y_past + (size_t)b * N * D2);
    const float4* sq4 = reinterpret_cast<const float4*>(sq);

    // q fragment for this lane's chunks (registers)
    const float4 q0 = sq4[c];
    const float4 q1 = sq4[c + 8];
    const float4 q2 = sq4[c + 16];
    const float4 q3 = sq4[c + 24];

    // Front-batch all 16 independent streaming loads (MLP 16)
    float4 v[4][4];
#pragma unroll
    for (int t = 0; t < 4; t++) {
#pragma unroll
        for (int k = 0; k < 4; k++) {
            v[t][k] = __ldcs(&base[(size_t)(row0 + t) * 32 + c + 8 * k]);
        }
    }

    float acc[4];
#pragma unroll
    for (int t = 0; t < 4; t++) {
        float a;
        a = fmaf(v[t][0].x, q0.x, fmaf(v[t][0].y, q0.y, fmaf(v[t][0].z, q0.z, v[t][0].w * q0.w)));
        a = fmaf(v[t][1].x, q1.x, fmaf(v[t][1].y, q1.y, fmaf(v[t][1].z, q1.z, fmaf(v[t][1].w, q1.w, a))));
        a = fmaf(v[t][2].x, q2.x, fmaf(v[t][2].y, q2.y, fmaf(v[t][2].z, q2.z, fmaf(v[t][2].w, q2.w, a))));
        a = fmaf(v[t][3].x, q3.x, fmaf(v[t][3].y, q3.y, fmaf(v[t][3].z, q3.z, fmaf(v[t][3].w, q3.w, a))));
        acc[t] = a;
    }

    // Reduce over the 8 chunk-lanes (xor 1,2,4 stays within the 8-lane group)
#pragma unroll
    for (int o = 1; o <= 4; o <<= 1) {
#pragma unroll
        for (int t = 0; t < 4; t++) {
            acc[t] += __shfl_xor_sync(0xffffffffu, acc[t], o);
        }
    }

    if (c == 0) {
        *reinterpret_cast<float4*>(g_logits + (size_t)b * N + row0) =
            make_float4(acc[0], acc[1], acc[2], acc[3]);
    }
}

// ---------------------------------------------------------------------------
// K3: per-batch softmax over N logits + scatter-add into S bins, normalize.
// grid = B, block = 1024, dynamic smem = S floats (bins)
// ---------------------------------------------------------------------------
__global__ __launch_bounds__(1024) void softmax_scatter_kernel(const int* __restrict__ s_past,
                                                               float* __restrict__ out,
                                                               int N, int S) {
    extern __shared__ float bins[];          // S floats
    __shared__ float red[32];
    __shared__ float bcast;

    const int b = blockIdx.x;
    const int t = threadIdx.x;
    const int T = blockDim.x;                // 1024
    const int per = N / T;                   // 4

    for (int s = t; s < S; s += T) bins[s] = 0.f;

    // Front-batch ALL loads (logits L2-hot + s_past DRAM gather)
    float vals[8];
    int   sid[8];
    float mx = -CUDART_INF_F;
#pragma unroll 4
    for (int i = 0; i < per; i++) {
        vals[i] = g_logits[(size_t)b * N + t + i * T];
        sid[i]  = __ldcs(&s_past[(size_t)b * N + t + i * T]);
    }
#pragma unroll 4
    for (int i = 0; i < per; i++) mx = fmaxf(mx, vals[i]);

    // block-reduce max
#pragma unroll
    for (int o = 16; o; o >>= 1) mx = fmaxf(mx, __shfl_xor_sync(0xffffffffu, mx, o));
    if ((t & 31) == 0) red[t >> 5] = mx;
    __syncthreads();
    if (t < 32) {
        float m = (t < T / 32) ? red[t] : -CUDART_INF_F;
#pragma unroll
        for (int o = 16; o; o >>= 1) m = fmaxf(m, __shfl_xor_sync(0xffffffffu, m, o));
        if (t == 0) bcast = m;
    }
    __syncthreads();
    mx = bcast;

    // exp, local sum, scatter into shared bins
    float sum = 0.f;
#pragma unroll 4
    for (int i = 0; i < per; i++) {
        float e = __expf(vals[i] - mx);
        sum += e;
        atomicAdd(&bins[sid[i]], e);
    }
    __syncthreads();

    // block-reduce sum
#pragma unroll
    for (int o = 16; o; o >>= 1) sum += __shfl_xor_sync(0xffffffffu, sum, o);
    if ((t & 31) == 0) red[t >> 5] = sum;
    __syncthreads();
    if (t < 32) {
        float s2 = (t < T / 32) ? red[t] : 0.f;
#pragma unroll
        for (int o = 16; o; o >>= 1) s2 += __shfl_xor_sync(0xffffffffu, s2, o);
        if (t == 0) bcast = s2;
    }
    __syncthreads();
    const float inv_z = 1.0f / bcast;

    for (int s = t; s < S; s += T) {
        out[(size_t)b * S + s] = bins[s] * inv_z;
    }
}

// ---------------------------------------------------------------------------
// kernel_launch
// ---------------------------------------------------------------------------
extern "C" void kernel_launch(void* const* d_in, const int* in_sizes, int n_in,
                              void* d_out, int out_size) {
    const int*   s_past = (const int*)d_in[0];
    const float* yq     = (const float*)d_in[1];
    const float* y_past = (const float*)d_in[2];
    const float* w_mat  = (const float*)d_in[3];
    float*       out    = (float*)d_out;

    const int D = D2;                       // 128 (w_mat is D2 x D2)
    const int B = in_sizes[1] / D;          // 64
    const int N = in_sizes[0] / B;          // 4096
    const int S = out_size / B;             // 512

    qproj_kernel<<<dim3(B, ECH), D>>>(yq, w_mat);

    dim3 grid2(N / 128, B);
    logits_kernel<<<grid2, 256>>>(y_past, N);

    softmax_scatter_kernel<<<B, 1024, S * sizeof(float)>>>(s_past, out, N, S);
}

// round 6
// speedup vs baseline: 1.0191x; 1.0191x over previous
#include <cuda_runtime.h>
#include <math_constants.h>

// Problem shape (fixed by the dataset): B=64, N=4096, D2=128, S=512
#define D2 128
#define MAXB 64
#define MAXN 4096
#define ECH 8          // e-chunks for qproj
#define SLICES 16      // K2 blocks per batch
#define ITERS 4        // tiles per K2 block (64 rows each)

// Scratch (no cudaMalloc allowed)
__device__ float g_qpart[ECH][MAXB * D2];   // 8 partial q arrays (256 KB)
__device__ float g_logits[MAXB * MAXN];     // 1 MB

// ---------------------------------------------------------------------------
// K1: partial q: g_qpart[c][b,d] = sum_{e in chunk c} yq[b,e] * w[e,d]
// grid = (B, ECH), block = 128. Final 8-way reduce folded into K2's prologue.
// ---------------------------------------------------------------------------
__global__ __launch_bounds__(128) void qproj_kernel(const float* __restrict__ yq,
                                                    const float* __restrict__ w) {
    const int b = blockIdx.x;
    const int c = blockIdx.y;
    const int d = threadIdx.x;     // 0..127
    __shared__ float syq[D2 / ECH];    // 16
    if (d < D2 / ECH) syq[d] = yq[b * D2 + c * (D2 / ECH) + d];
    __syncthreads();

    const int e0 = c * (D2 / ECH);
    float acc = 0.f;
#pragma unroll
    for (int j = 0; j < D2 / ECH; j++) {
        acc = fmaf(syq[j], w[(e0 + j) * D2 + d], acc);
    }
    g_qpart[c][b * D2 + d] = acc;
}

// ---------------------------------------------------------------------------
// K2: logits[b,n] = q[b] . y_past[b,n]
// Persistent-ish: each block owns 256 rows (4 iterations x 64 rows), so the
// sq prologue amortizes and the load stream never drains between tiles.
// Lane layout: c = lane&7 (float4 chunk), g = lane>>3 (row pair).
// Per iter per thread: 8 front-batched streaming LDG.128, 6 SHFL, 1 STG.64.
// Block = 256 threads = 8 warps = 64 rows/iter. grid = (SLICES, B).
// ---------------------------------------------------------------------------
__global__ __launch_bounds__(256) void logits_kernel(const float* __restrict__ y_past, int N) {
    const int b = blockIdx.y;
    __shared__ float sq[D2];
    if (threadIdx.x < D2) {
        float s = 0.f;
#pragma unroll
        for (int p = 0; p < ECH; p++) s += g_qpart[p][b * D2 + threadIdx.x];
        sq[threadIdx.x] = s;
    }
    __syncthreads();

    const int warp = threadIdx.x >> 5;     // 0..7
    const int lane = threadIdx.x & 31;
    const int g = lane >> 3;               // 0..3  (row pair within warp)
    const int c = lane & 7;                // 0..7  (chunk within row)

    const float4* __restrict__ base =
        reinterpret_cast<const float4*>(y_past + (size_t)b * N * D2);
    const float4* sq4 = reinterpret_cast<const float4*>(sq);

    // q fragment for this lane's chunks (registers)
    const float4 q0 = sq4[c];
    const float4 q1 = sq4[c + 8];
    const float4 q2 = sq4[c + 16];
    const float4 q3 = sq4[c + 24];

    const int rows_per_block = ITERS * 64;               // 256
    const int block_row0 = blockIdx.x * rows_per_block;

#pragma unroll
    for (int it = 0; it < ITERS; it++) {
        const int row0 = block_row0 + it * 64 + warp * 8 + g * 2;

        // Front-batch 8 independent streaming loads (2 rows x 4 chunks)
        float4 v0 = __ldcs(&base[(size_t)(row0 + 0) * 32 + c]);
        float4 v1 = __ldcs(&base[(size_t)(row0 + 0) * 32 + c + 8]);
        float4 v2 = __ldcs(&base[(size_t)(row0 + 0) * 32 + c + 16]);
        float4 v3 = __ldcs(&base[(size_t)(row0 + 0) * 32 + c + 24]);
        float4 u0 = __ldcs(&base[(size_t)(row0 + 1) * 32 + c]);
        float4 u1 = __ldcs(&base[(size_t)(row0 + 1) * 32 + c + 8]);
        float4 u2 = __ldcs(&base[(size_t)(row0 + 1) * 32 + c + 16]);
        float4 u3 = __ldcs(&base[(size_t)(row0 + 1) * 32 + c + 24]);

        float a0, a1;
        a0 = fmaf(v0.x, q0.x, fmaf(v0.y, q0.y, fmaf(v0.z, q0.z, v0.w * q0.w)));
        a0 = fmaf(v1.x, q1.x, fmaf(v1.y, q1.y, fmaf(v1.z, q1.z, fmaf(v1.w, q1.w, a0))));
        a0 = fmaf(v2.x, q2.x, fmaf(v2.y, q2.y, fmaf(v2.z, q2.z, fmaf(v2.w, q2.w, a0))));
        a0 = fmaf(v3.x, q3.x, fmaf(v3.y, q3.y, fmaf(v3.z, q3.z, fmaf(v3.w, q3.w, a0))));
        a1 = fmaf(u0.x, q0.x, fmaf(u0.y, q0.y, fmaf(u0.z, q0.z, u0.w * q0.w)));
        a1 = fmaf(u1.x, q1.x, fmaf(u1.y, q1.y, fmaf(u1.z, q1.z, fmaf(u1.w, q1.w, a1))));
        a1 = fmaf(u2.x, q2.x, fmaf(u2.y, q2.y, fmaf(u2.z, q2.z, fmaf(u2.w, q2.w, a1))));
        a1 = fmaf(u3.x, q3.x, fmaf(u3.y, q3.y, fmaf(u3.z, q3.z, fmaf(u3.w, q3.w, a1))));

        // Reduce over the 8 chunk-lanes (xor 1,2,4 stays within the group)
#pragma unroll
        for (int o = 1; o <= 4; o <<= 1) {
            a0 += __shfl_xor_sync(0xffffffffu, a0, o);
            a1 += __shfl_xor_sync(0xffffffffu, a1, o);
        }

        if (c == 0) {
            *reinterpret_cast<float2*>(g_logits + (size_t)b * N + row0) =
                make_float2(a0, a1);
        }
    }
}

// ---------------------------------------------------------------------------
// K3: per-batch softmax over N logits + scatter-add into S bins, normalize.
// grid = B, block = 1024, dynamic smem = S floats (bins)
// ---------------------------------------------------------------------------
__global__ __launch_bounds__(1024) void softmax_scatter_kernel(const int* __restrict__ s_past,
                                                               float* __restrict__ out,
                                                               int N, int S) {
    extern __shared__ float bins[];          // S floats
    __shared__ float red[32];
    __shared__ float bcast;

    const int b = blockIdx.x;
    const int t = threadIdx.x;
    const int T = blockDim.x;                // 1024
    const int per = N / T;                   // 4

    for (int s = t; s < S; s += T) bins[s] = 0.f;

    // Front-batch ALL loads (logits L2-hot + s_past DRAM gather)
    float vals[8];
    int   sid[8];
    float mx = -CUDART_INF_F;
#pragma unroll 4
    for (int i = 0; i < per; i++) {
        vals[i] = g_logits[(size_t)b * N + t + i * T];
        sid[i]  = __ldcs(&s_past[(size_t)b * N + t + i * T]);
    }
#pragma unroll 4
    for (int i = 0; i < per; i++) mx = fmaxf(mx, vals[i]);

    // block-reduce max
#pragma unroll
    for (int o = 16; o; o >>= 1) mx = fmaxf(mx, __shfl_xor_sync(0xffffffffu, mx, o));
    if ((t & 31) == 0) red[t >> 5] = mx;
    __syncthreads();
    if (t < 32) {
        float m = (t < T / 32) ? red[t] : -CUDART_INF_F;
#pragma unroll
        for (int o = 16; o; o >>= 1) m = fmaxf(m, __shfl_xor_sync(0xffffffffu, m, o));
        if (t == 0) bcast = m;
    }
    __syncthreads();
    mx = bcast;

    // exp, local sum, scatter into shared bins
    float sum = 0.f;
#pragma unroll 4
    for (int i = 0; i < per; i++) {
        float e = __expf(vals[i] - mx);
        sum += e;
        atomicAdd(&bins[sid[i]], e);
    }
    __syncthreads();

    // block-reduce sum
#pragma unroll
    for (int o = 16; o; o >>= 1) sum += __shfl_xor_sync(0xffffffffu, sum, o);
    if ((t & 31) == 0) red[t >> 5] = sum;
    __syncthreads();
    if (t < 32) {
        float s2 = (t < T / 32) ? red[t] : 0.f;
#pragma unroll
        for (int o = 16; o; o >>= 1) s2 += __shfl_xor_sync(0xffffffffu, s2, o);
        if (t == 0) bcast = s2;
    }
    __syncthreads();
    const float inv_z = 1.0f / bcast;

    for (int s = t; s < S; s += T) {
        out[(size_t)b * S + s] = bins[s] * inv_z;
    }
}

// ---------------------------------------------------------------------------
// kernel_launch
// ---------------------------------------------------------------------------
extern "C" void kernel_launch(void* const* d_in, const int* in_sizes, int n_in,
                              void* d_out, int out_size) {
    const int*   s_past = (const int*)d_in[0];
    const float* yq     = (const float*)d_in[1];
    const float* y_past = (const float*)d_in[2];
    const float* w_mat  = (const float*)d_in[3];
    float*       out    = (float*)d_out;

    const int D = D2;                       // 128 (w_mat is D2 x D2)
    const int B = in_sizes[1] / D;          // 64
    const int N = in_sizes[0] / B;          // 4096
    const int S = out_size / B;             // 512

    qproj_kernel<<<dim3(B, ECH), D>>>(yq, w_mat);

    dim3 grid2(SLICES, B);                  // 16 x 64 = 1024 blocks, 256 rows each
    logits_kernel<<<grid2, 256>>>(y_past, N);

    softmax_scatter_kernel<<<B, 1024, S * sizeof(float)>>>(s_past, out, N, S);
}